// round 6
// baseline (speedup 1.0000x reference)
#include <cuda_runtime.h>
#include <cuda_fp16.h>
#include <cstdint>

#define BB   32
#define SS   2048
#define ND   1024

// Scratch (allocation-free rule: __device__ globals)
__device__ float  g_scores[BB * SS];
__device__ float  g_decb[BB * ND];
__device__ __half g_Bth[ND * ND];         // W_enc^T fp16: Bth[n][k] = W[1024+k][n]
__device__ __half g_ench[BB * SS * ND];   // encoder_outputs in fp16

// ---------------------------------------------------------------- helpers
__device__ __forceinline__ float fast_tanh(float x) {
    float y;
    asm("tanh.approx.f32 %0, %1;" : "=f"(y) : "f"(x));
    return y;
}
__device__ __forceinline__ uint32_t smem_u32(const void* p) {
    uint32_t a;
    asm("{ .reg .u64 t; cvta.to.shared.u64 t, %1; cvt.u32.u64 %0, t; }" : "=r"(a) : "l"(p));
    return a;
}

// ---------------------------------------------------------------------------
// Kernel A: convert encoder_outputs fp32 -> fp16 (64M elements)
// ---------------------------------------------------------------------------
__global__ void convert_kernel(const float* __restrict__ enc) {
    const uint32_t t = blockIdx.x * 256 + threadIdx.x;     // 2M threads
    uint2* outp = (uint2*)g_ench;
#pragma unroll
    for (int i = 0; i < 8; i++) {
        const uint32_t idx = t + (uint32_t)i * (8192 * 256);   // float4 index
        const float4 v = *(const float4*)(enc + (size_t)idx * 4);
        __half2 h0 = __floats2half2_rn(v.x, v.y);
        __half2 h1 = __floats2half2_rn(v.z, v.w);
        uint2 o;
        o.x = *(uint32_t*)&h0;
        o.y = *(uint32_t*)&h1;
        outp[idx] = o;
    }
}

// ---------------------------------------------------------------------------
// Kernel 0: transpose W_enc -> g_Bth (fp16)
// ---------------------------------------------------------------------------
__global__ void transpose_kernel(const float* __restrict__ W) {
    __shared__ float t[32][33];
    const int kb = blockIdx.x * 32, nb = blockIdx.y * 32;
    const int tx = threadIdx.x, ty = threadIdx.y;
#pragma unroll
    for (int i = 0; i < 32; i += 8)
        t[ty + i][tx] = W[(size_t)(1024 + kb + ty + i) * 1024 + nb + tx];
    __syncthreads();
#pragma unroll
    for (int i = 0; i < 32; i += 8)
        g_Bth[(size_t)(nb + ty + i) * 1024 + kb + tx] = __float2half_rn(t[tx][ty + i]);
}

// ---------------------------------------------------------------------------
// Kernel 1: dec_base = dh @ W_dec + b_attn; zero score scratch + ctx output
//   grid = (32 b, 4 d-chunks), 256 threads: each thread one d column.
// ---------------------------------------------------------------------------
__global__ void prep_kernel(const float* __restrict__ dh,
                            const float* __restrict__ W,
                            const float* __restrict__ b_attn,
                            float* __restrict__ out_ctx) {
    const int b   = blockIdx.x;
    const int dc  = blockIdx.y;
    const int tid = threadIdx.x;
    const int blk = b * 4 + dc;

    for (int i = blk * 256 + tid; i < BB * SS; i += 128 * 256) g_scores[i] = 0.f;
    for (int i = blk * 256 + tid; i < BB * ND; i += 128 * 256) out_ctx[i] = 0.f;

    __shared__ float sh[ND];
    for (int i = tid; i < ND; i += 256) sh[i] = dh[b * ND + i];
    __syncthreads();

    const int d0 = dc * 256 + tid;
    float a = b_attn[d0];
#pragma unroll 8
    for (int e = 0; e < ND; e++)
        a += sh[e] * W[(size_t)e * ND + d0];
    g_decb[b * ND + d0] = a;
}

// ---------------------------------------------------------------------------
// Kernel 2: enc_proj GEMM, all-fp16 operands (mma.sync m16n8k16), 128x128
//   tile, BK=32, double-buffered cp.async, fused tanh + v-dot.
//   A and B smem: 64B rows (32 halfs), no pad -> phase-conflict-free LDS.128.
//   K-permutation identical on A and B (exact): thread k-window = (lane&3)*8.
// ---------------------------------------------------------------------------
#define STB       8192                     // bytes per stage (A or B)
#define GEMM_SMEM (4 * STB)

__global__ __launch_bounds__(256, 2) void score_gemm(const float* __restrict__ vw) {
    extern __shared__ char smc[];
    const uint32_t sb = smem_u32(smc);
    const int tid  = threadIdx.x;
    const int lane = tid & 31;
    const int warp = tid >> 5;
    const int wm   = warp >> 1;              // 0..3
    const int wn   = warp & 1;               // 0..1
    const int n0   = blockIdx.x * 128;
    const int m0   = blockIdx.y * 128;

    const __half* Abase = g_ench + (size_t)m0 * 1024;
    const __half* Bbase = g_Bth + (size_t)n0 * 1024;

    auto load_stage = [&](int kt, int st) {
        const uint32_t abase = sb + (uint32_t)(st * STB);
        const uint32_t bbase = sb + (uint32_t)((2 + st) * STB);
        const __half* Ag = Abase + kt * 32;
        const __half* Bg = Bbase + kt * 32;
#pragma unroll
        for (int i = 0; i < 2; i++) {
            const int q = tid + i * 256;     // 0..511
            const int r = q >> 2, c = q & 3; // row 0..127, 16B chunk 0..3
            asm volatile("cp.async.cg.shared.global [%0], [%1], 16;"
                         :: "r"(abase + (uint32_t)(r * 64 + c * 16)),
                            "l"(Ag + (size_t)r * 1024 + c * 8));
            asm volatile("cp.async.cg.shared.global [%0], [%1], 16;"
                         :: "r"(bbase + (uint32_t)(r * 64 + c * 16)),
                            "l"(Bg + (size_t)r * 1024 + c * 8));
        }
        asm volatile("cp.async.commit_group;" ::: "memory");
    };

    float acc[2][8][4];
#pragma unroll
    for (int i = 0; i < 2; i++)
#pragma unroll
        for (int j = 0; j < 8; j++)
#pragma unroll
            for (int c = 0; c < 4; c++) acc[i][j][c] = 0.f;

    load_stage(0, 0);
    load_stage(1, 1);

    const uint32_t koff = (lane & 3) * 16;   // byte offset of k-window in row
    const int ra = wm * 32 + (lane >> 2);    // A base row
    const int nb = wn * 64 + (lane >> 2);    // B base col

    for (int kt = 0; kt < 32; kt++) {
        const int st = kt & 1;
        if (kt < 30)
            asm volatile("cp.async.wait_group 1;" ::: "memory");
        else
            asm volatile("cp.async.wait_group 0;" ::: "memory");
        __syncthreads();

        const uint32_t Asb = sb + (uint32_t)(st * STB);
        const uint32_t Bsb = sb + (uint32_t)((2 + st) * STB);

        // A fragments: rows ra+{0,8,16,24}, 8 contiguous halfs each (1 LDS.128)
        uint32_t ah[4][4];
#pragma unroll
        for (int rdx = 0; rdx < 4; rdx++) {
            const uint32_t addr = Asb + (uint32_t)((ra + 8 * rdx) * 64) + koff;
            asm volatile("ld.shared.v4.u32 {%0,%1,%2,%3}, [%4];"
                         : "=r"(ah[rdx][0]), "=r"(ah[rdx][1]),
                           "=r"(ah[rdx][2]), "=r"(ah[rdx][3])
                         : "r"(addr));
        }

#pragma unroll
        for (int jh = 0; jh < 2; jh++) {
            uint32_t bh[4][4];
#pragma unroll
            for (int j = 0; j < 4; j++) {
                const uint32_t addr =
                    Bsb + (uint32_t)((nb + (jh * 4 + j) * 8) * 64) + koff;
                asm volatile("ld.shared.v4.u32 {%0,%1,%2,%3}, [%4];"
                             : "=r"(bh[j][0]), "=r"(bh[j][1]),
                               "=r"(bh[j][2]), "=r"(bh[j][3])
                             : "r"(addr));
            }
#pragma unroll
            for (int i = 0; i < 2; i++)
#pragma unroll
                for (int j = 0; j < 4; j++)
#pragma unroll
                    for (int s = 0; s < 2; s++) {
                        const int jj = jh * 4 + j;
                        asm volatile(
                            "mma.sync.aligned.m16n8k16.row.col.f32.f16.f16.f32 "
                            "{%0,%1,%2,%3}, {%4,%5,%6,%7}, {%8,%9}, {%0,%1,%2,%3};"
                            : "+f"(acc[i][jj][0]), "+f"(acc[i][jj][1]),
                              "+f"(acc[i][jj][2]), "+f"(acc[i][jj][3])
                            : "r"(ah[2 * i][2 * s]), "r"(ah[2 * i + 1][2 * s]),
                              "r"(ah[2 * i][2 * s + 1]), "r"(ah[2 * i + 1][2 * s + 1]),
                              "r"(bh[j][2 * s]), "r"(bh[j][2 * s + 1]));
                    }
        }
        __syncthreads();
        if (kt + 2 < 32) load_stage(kt + 2, st);
    }

    // Epilogue: energy = tanh(acc + dec_base[b][col]); score partial = energy . v_w
    const int b = m0 >> 11;
    float eadd[16], vv[16];
#pragma unroll
    for (int j = 0; j < 8; j++)
#pragma unroll
        for (int c = 0; c < 2; c++) {
            const int col = n0 + wn * 64 + j * 8 + (lane & 3) * 2 + c;
            eadd[j * 2 + c] = g_decb[b * ND + col];
            vv[j * 2 + c]   = vw[col];
        }

#pragma unroll
    for (int i = 0; i < 2; i++)
#pragma unroll
        for (int h = 0; h < 2; h++) {
            float p = 0.f;
#pragma unroll
            for (int j = 0; j < 8; j++)
#pragma unroll
                for (int c = 0; c < 2; c++)
                    p += fast_tanh(acc[i][j][h * 2 + c] + eadd[j * 2 + c]) * vv[j * 2 + c];
            p += __shfl_xor_sync(0xffffffffu, p, 1);
            p += __shfl_xor_sync(0xffffffffu, p, 2);
            if ((lane & 3) == 0) {
                const int row = m0 + wm * 32 + i * 16 + h * 8 + (lane >> 2);
                atomicAdd(&g_scores[row], p);
            }
        }
}

// ---------------------------------------------------------------------------
// Kernel 3: masked softmax over S per batch
// ---------------------------------------------------------------------------
__global__ void softmax_kernel(const int* __restrict__ mask,
                               float* __restrict__ out_w) {
    const int b = blockIdx.x;
    const int tid = threadIdx.x;
    __shared__ float red[256];

    float ls[8];
#pragma unroll
    for (int i = 0; i < 8; i++) {
        const int s = tid + i * 256;
        const float sc = g_scores[b * SS + s];
        ls[i] = (mask[b * SS + s] == 0) ? -1e9f : sc;
    }
    float mx = ls[0];
#pragma unroll
    for (int i = 1; i < 8; i++) mx = fmaxf(mx, ls[i]);
    red[tid] = mx;
    __syncthreads();
    for (int off = 128; off > 0; off >>= 1) {
        if (tid < off) red[tid] = fmaxf(red[tid], red[tid + off]);
        __syncthreads();
    }
    mx = red[0];
    __syncthreads();

    float ex[8];
    float sum = 0.f;
#pragma unroll
    for (int i = 0; i < 8; i++) {
        ex[i] = __expf(ls[i] - mx);
        sum += ex[i];
    }
    red[tid] = sum;
    __syncthreads();
    for (int off = 128; off > 0; off >>= 1) {
        if (tid < off) red[tid] += red[tid + off];
        __syncthreads();
    }
    const float inv = 1.f / red[0];
#pragma unroll
    for (int i = 0; i < 8; i++)
        out_w[b * SS + tid + i * 256] = ex[i] * inv;
}

// ---------------------------------------------------------------------------
// Kernel 4: context = attn_weights @ encoder_outputs (fp16 enc, fp32 accum)
// ---------------------------------------------------------------------------
__global__ void context_kernel(const float* __restrict__ w,
                               float* __restrict__ ctx) {
    const int b = blockIdx.y;
    const int ch = blockIdx.x;
    const int tid = threadIdx.x;
    __shared__ float ws[128];
    const int s0 = ch * 128;
    if (tid < 128) ws[tid] = w[b * SS + s0 + tid];
    __syncthreads();

    float ax = 0.f, ay = 0.f, az = 0.f, aw = 0.f;
    const __half* base = g_ench + ((size_t)b * SS + s0) * 1024 + tid * 4;
#pragma unroll 4
    for (int s = 0; s < 128; s++) {
        const uint2 u = *(const uint2*)(base + (size_t)s * 1024);
        const float2 f01 = __half22float2(*(const __half2*)&u.x);
        const float2 f23 = __half22float2(*(const __half2*)&u.y);
        const float wv = ws[s];
        ax += wv * f01.x;
        ay += wv * f01.y;
        az += wv * f23.x;
        aw += wv * f23.y;
    }
    float* o = ctx + b * ND + tid * 4;
    atomicAdd(o + 0, ax);
    atomicAdd(o + 1, ay);
    atomicAdd(o + 2, az);
    atomicAdd(o + 3, aw);
}

// ---------------------------------------------------------------------------
extern "C" void kernel_launch(void* const* d_in, const int* in_sizes, int n_in,
                              void* d_out, int out_size) {
    const float* dh   = (const float*)d_in[0];   // (32, 1024)
    const float* enc  = (const float*)d_in[1];   // (32, 2048, 1024)
    const int*   mask = (const int*)d_in[2];     // (32, 2048)
    const float* W    = (const float*)d_in[3];   // (2048, 1024)
    const float* ba   = (const float*)d_in[4];   // (1024,)
    const float* vw   = (const float*)d_in[5];   // (1024,)

    float* out  = (float*)d_out;
    float* ctx  = out;                 // (32, 1024)
    float* attw = out + BB * ND;       // (32, 2048)

    cudaFuncSetAttribute(score_gemm, cudaFuncAttributeMaxDynamicSharedMemorySize, GEMM_SMEM);

    convert_kernel<<<8192, 256>>>(enc);
    transpose_kernel<<<dim3(32, 32), dim3(32, 8)>>>(W);
    prep_kernel<<<dim3(32, 4), 256>>>(dh, W, ba, ctx);
    score_gemm<<<dim3(8, 512), 256, GEMM_SMEM>>>(vw);
    softmax_kernel<<<32, 256>>>(mask, attw);
    context_kernel<<<dim3(16, 32), 256>>>(attw, ctx);
}

// round 7
// speedup vs baseline: 1.0801x; 1.0801x over previous
#include <cuda_runtime.h>
#include <cuda_fp16.h>
#include <cstdint>

#define BB   32
#define SS   2048
#define ND   1024

// Scratch (allocation-free rule: __device__ globals)
__device__ float  g_scores[BB * SS];
__device__ float  g_decb[BB * ND];
__device__ __half g_Bth[ND * ND];         // W_enc^T fp16: Bth[n][k] = W[1024+k][n]
__device__ __half g_ench[BB * SS * ND];   // encoder_outputs in fp16

// ---------------------------------------------------------------- helpers
__device__ __forceinline__ float fast_tanh(float x) {
    float y;
    asm("tanh.approx.f32 %0, %1;" : "=f"(y) : "f"(x));
    return y;
}
__device__ __forceinline__ uint32_t smem_u32(const void* p) {
    uint32_t a;
    asm("{ .reg .u64 t; cvta.to.shared.u64 t, %1; cvt.u32.u64 %0, t; }" : "=r"(a) : "l"(p));
    return a;
}

// ---------------------------------------------------------------------------
// Kernel A: convert encoder_outputs fp32 -> fp16 (64M elements)
// ---------------------------------------------------------------------------
__global__ void convert_kernel(const float* __restrict__ enc) {
    const uint32_t t = blockIdx.x * 256 + threadIdx.x;     // 2M threads
    uint2* outp = (uint2*)g_ench;
#pragma unroll
    for (int i = 0; i < 8; i++) {
        const uint32_t idx = t + (uint32_t)i * (8192 * 256);   // float4 index
        const float4 v = *(const float4*)(enc + (size_t)idx * 4);
        __half2 h0 = __floats2half2_rn(v.x, v.y);
        __half2 h1 = __floats2half2_rn(v.z, v.w);
        uint2 o;
        o.x = *(uint32_t*)&h0;
        o.y = *(uint32_t*)&h1;
        outp[idx] = o;
    }
}

// ---------------------------------------------------------------------------
// Kernel 0: transpose W_enc -> g_Bth (fp16)
// ---------------------------------------------------------------------------
__global__ void transpose_kernel(const float* __restrict__ W) {
    __shared__ float t[32][33];
    const int kb = blockIdx.x * 32, nb = blockIdx.y * 32;
    const int tx = threadIdx.x, ty = threadIdx.y;
#pragma unroll
    for (int i = 0; i < 32; i += 8)
        t[ty + i][tx] = W[(size_t)(1024 + kb + ty + i) * 1024 + nb + tx];
    __syncthreads();
#pragma unroll
    for (int i = 0; i < 32; i += 8)
        g_Bth[(size_t)(nb + ty + i) * 1024 + kb + tx] = __float2half_rn(t[tx][ty + i]);
}

// ---------------------------------------------------------------------------
// Kernel 1: dec_base = dh @ W_dec + b_attn; zero score scratch + ctx output
// ---------------------------------------------------------------------------
__global__ void prep_kernel(const float* __restrict__ dh,
                            const float* __restrict__ W,
                            const float* __restrict__ b_attn,
                            float* __restrict__ out_ctx) {
    const int b   = blockIdx.x;
    const int dc  = blockIdx.y;
    const int tid = threadIdx.x;
    const int blk = b * 4 + dc;

    for (int i = blk * 256 + tid; i < BB * SS; i += 128 * 256) g_scores[i] = 0.f;
    for (int i = blk * 256 + tid; i < BB * ND; i += 128 * 256) out_ctx[i] = 0.f;

    __shared__ float sh[ND];
    for (int i = tid; i < ND; i += 256) sh[i] = dh[b * ND + i];
    __syncthreads();

    const int d0 = dc * 256 + tid;
    float a = b_attn[d0];
#pragma unroll 8
    for (int e = 0; e < ND; e++)
        a += sh[e] * W[(size_t)e * ND + d0];
    g_decb[b * ND + d0] = a;
}

// ---------------------------------------------------------------------------
// Kernel 2: enc_proj GEMM, all-fp16 mma.sync m16n8k16, 128x128 tile, BK=32,
//   4-stage cp.async ring, ONE __syncthreads per kt, fused tanh + v-dot.
//   Ring safety: sync at top of iter kt guarantees all warps finished reading
//   stage (kt-1)&3 == (kt+3)&3, so issuing loads into stage (kt+3)&3 after
//   the sync is race-free. Uniform commit_group per kt keeps wait_group 2
//   exact (stage kt = commit group kt+1; outstanding<=2 => group kt+1 done).
//   A,B smem: 64B rows, no pad -> conflict-free LDS.128.
//   K-permutation identical on A and B (exact): thread k-window = (lane&3)*8.
// ---------------------------------------------------------------------------
#define STB       8192                     // bytes per stage (A or B)
#define BOFS      (4 * STB)                // B region starts after 4 A stages
#define GEMM_SMEM (8 * STB)                // 64 KB

__global__ __launch_bounds__(256, 2) void score_gemm(const float* __restrict__ vw) {
    extern __shared__ char smc[];
    const uint32_t sb = smem_u32(smc);
    const int tid  = threadIdx.x;
    const int lane = tid & 31;
    const int warp = tid >> 5;
    const int wm   = warp >> 1;              // 0..3
    const int wn   = warp & 1;               // 0..1
    const int n0   = blockIdx.x * 128;
    const int m0   = blockIdx.y * 128;

    // per-thread gmem src pointers (2 16B-chunks each for A and B per stage)
    const int r0 = tid >> 2, c0 = tid & 3;   // row 0..63, 16B chunk 0..3
    const char* pa0 = (const char*)(g_ench + (size_t)(m0 + r0) * 1024 + c0 * 8);
    const char* pa1 = pa0 + 64 * 1024 * 2;   // rows 64..127
    const char* pb0 = (const char*)(g_Bth + (size_t)(n0 + r0) * 1024 + c0 * 8);
    const char* pb1 = pb0 + 64 * 1024 * 2;
    // per-thread smem dst offsets (stage-relative)
    const uint32_t dA0 = sb + (uint32_t)tid * 16;
    const uint32_t dA1 = dA0 + 4096;
    const uint32_t dB0 = sb + BOFS + (uint32_t)tid * 16;
    const uint32_t dB1 = dB0 + 4096;

#define LOAD_STAGE(kt, st)                                                     \
    do {                                                                       \
        const uint32_t so = (uint32_t)(st) * STB;                              \
        const int kb_ = (kt) * 64;                                             \
        asm volatile("cp.async.cg.shared.global [%0], [%1], 16;"               \
                     :: "r"(dA0 + so), "l"(pa0 + kb_));                        \
        asm volatile("cp.async.cg.shared.global [%0], [%1], 16;"               \
                     :: "r"(dA1 + so), "l"(pa1 + kb_));                        \
        asm volatile("cp.async.cg.shared.global [%0], [%1], 16;"               \
                     :: "r"(dB0 + so), "l"(pb0 + kb_));                        \
        asm volatile("cp.async.cg.shared.global [%0], [%1], 16;"               \
                     :: "r"(dB1 + so), "l"(pb1 + kb_));                        \
    } while (0)

    float acc[2][8][4];
#pragma unroll
    for (int i = 0; i < 2; i++)
#pragma unroll
        for (int j = 0; j < 8; j++)
#pragma unroll
            for (int c = 0; c < 4; c++) acc[i][j][c] = 0.f;

    // preamble: stages 0,1,2 in flight (3 commit groups)
    LOAD_STAGE(0, 0);
    asm volatile("cp.async.commit_group;" ::: "memory");
    LOAD_STAGE(1, 1);
    asm volatile("cp.async.commit_group;" ::: "memory");
    LOAD_STAGE(2, 2);
    asm volatile("cp.async.commit_group;" ::: "memory");

    const uint32_t koff = (lane & 3) * 16;             // byte offset of k-window
    const uint32_t aoff = (uint32_t)(wm * 32 + (lane >> 2)) * 64 + koff;
    const uint32_t boff = (uint32_t)(wn * 64 + (lane >> 2)) * 64 + koff;

#pragma unroll 4
    for (int kt = 0; kt < 32; kt++) {
        const int st = kt & 3;                          // compile-time in body
        asm volatile("cp.async.wait_group 2;" ::: "memory");
        __syncthreads();

        const uint32_t Asb = sb + (uint32_t)st * STB + aoff;
        const uint32_t Bsb = sb + BOFS + (uint32_t)st * STB + boff;

        uint32_t ah[4][4];
#pragma unroll
        for (int rdx = 0; rdx < 4; rdx++)
            asm volatile("ld.shared.v4.u32 {%0,%1,%2,%3}, [%4];"
                         : "=r"(ah[rdx][0]), "=r"(ah[rdx][1]),
                           "=r"(ah[rdx][2]), "=r"(ah[rdx][3])
                         : "r"(Asb + rdx * 512));

#pragma unroll
        for (int jh = 0; jh < 2; jh++) {
            uint32_t bh[4][4];
#pragma unroll
            for (int j = 0; j < 4; j++)
                asm volatile("ld.shared.v4.u32 {%0,%1,%2,%3}, [%4];"
                             : "=r"(bh[j][0]), "=r"(bh[j][1]),
                               "=r"(bh[j][2]), "=r"(bh[j][3])
                             : "r"(Bsb + (jh * 4 + j) * 512));
#pragma unroll
            for (int i = 0; i < 2; i++)
#pragma unroll
                for (int j = 0; j < 4; j++)
#pragma unroll
                    for (int s = 0; s < 2; s++) {
                        const int jj = jh * 4 + j;
                        asm volatile(
                            "mma.sync.aligned.m16n8k16.row.col.f32.f16.f16.f32 "
                            "{%0,%1,%2,%3}, {%4,%5,%6,%7}, {%8,%9}, {%0,%1,%2,%3};"
                            : "+f"(acc[i][jj][0]), "+f"(acc[i][jj][1]),
                              "+f"(acc[i][jj][2]), "+f"(acc[i][jj][3])
                            : "r"(ah[2 * i][2 * s]), "r"(ah[2 * i + 1][2 * s]),
                              "r"(ah[2 * i][2 * s + 1]), "r"(ah[2 * i + 1][2 * s + 1]),
                              "r"(bh[j][2 * s]), "r"(bh[j][2 * s + 1]));
                    }
        }

        if (kt < 29) LOAD_STAGE(kt + 3, (kt + 3) & 3);
        asm volatile("cp.async.commit_group;" ::: "memory");   // may be empty
    }
#undef LOAD_STAGE

    // Epilogue: energy = tanh(acc + dec_base[b][col]); score partial = energy . v_w
    const int b = m0 >> 11;
    float eadd[16], vv[16];
#pragma unroll
    for (int j = 0; j < 8; j++)
#pragma unroll
        for (int c = 0; c < 2; c++) {
            const int col = n0 + wn * 64 + j * 8 + (lane & 3) * 2 + c;
            eadd[j * 2 + c] = g_decb[b * ND + col];
            vv[j * 2 + c]   = vw[col];
        }

#pragma unroll
    for (int i = 0; i < 2; i++)
#pragma unroll
        for (int h = 0; h < 2; h++) {
            float p = 0.f;
#pragma unroll
            for (int j = 0; j < 8; j++)
#pragma unroll
                for (int c = 0; c < 2; c++)
                    p += fast_tanh(acc[i][j][h * 2 + c] + eadd[j * 2 + c]) * vv[j * 2 + c];
            p += __shfl_xor_sync(0xffffffffu, p, 1);
            p += __shfl_xor_sync(0xffffffffu, p, 2);
            if ((lane & 3) == 0) {
                const int row = m0 + wm * 32 + i * 16 + h * 8 + (lane >> 2);
                atomicAdd(&g_scores[row], p);
            }
        }
}

// ---------------------------------------------------------------------------
// Kernel 3: masked softmax over S per batch
// ---------------------------------------------------------------------------
__global__ void softmax_kernel(const int* __restrict__ mask,
                               float* __restrict__ out_w) {
    const int b = blockIdx.x;
    const int tid = threadIdx.x;
    __shared__ float red[256];

    float ls[8];
#pragma unroll
    for (int i = 0; i < 8; i++) {
        const int s = tid + i * 256;
        const float sc = g_scores[b * SS + s];
        ls[i] = (mask[b * SS + s] == 0) ? -1e9f : sc;
    }
    float mx = ls[0];
#pragma unroll
    for (int i = 1; i < 8; i++) mx = fmaxf(mx, ls[i]);
    red[tid] = mx;
    __syncthreads();
    for (int off = 128; off > 0; off >>= 1) {
        if (tid < off) red[tid] = fmaxf(red[tid], red[tid + off]);
        __syncthreads();
    }
    mx = red[0];
    __syncthreads();

    float ex[8];
    float sum = 0.f;
#pragma unroll
    for (int i = 0; i < 8; i++) {
        ex[i] = __expf(ls[i] - mx);
        sum += ex[i];
    }
    red[tid] = sum;
    __syncthreads();
    for (int off = 128; off > 0; off >>= 1) {
        if (tid < off) red[tid] += red[tid + off];
        __syncthreads();
    }
    const float inv = 1.f / red[0];
#pragma unroll
    for (int i = 0; i < 8; i++)
        out_w[b * SS + tid + i * 256] = ex[i] * inv;
}

// ---------------------------------------------------------------------------
// Kernel 4: context = attn_weights @ encoder_outputs (fp16 enc, fp32 accum)
// ---------------------------------------------------------------------------
__global__ void context_kernel(const float* __restrict__ w,
                               float* __restrict__ ctx) {
    const int b = blockIdx.y;
    const int ch = blockIdx.x;
    const int tid = threadIdx.x;
    __shared__ float ws[128];
    const int s0 = ch * 128;
    if (tid < 128) ws[tid] = w[b * SS + s0 + tid];
    __syncthreads();

    float ax = 0.f, ay = 0.f, az = 0.f, aw = 0.f;
    const __half* base = g_ench + ((size_t)b * SS + s0) * 1024 + tid * 4;
#pragma unroll 4
    for (int s = 0; s < 128; s++) {
        const uint2 u = *(const uint2*)(base + (size_t)s * 1024);
        const float2 f01 = __half22float2(*(const __half2*)&u.x);
        const float2 f23 = __half22float2(*(const __half2*)&u.y);
        const float wv = ws[s];
        ax += wv * f01.x;
        ay += wv * f01.y;
        az += wv * f23.x;
        aw += wv * f23.y;
    }
    float* o = ctx + b * ND + tid * 4;
    atomicAdd(o + 0, ax);
    atomicAdd(o + 1, ay);
    atomicAdd(o + 2, az);
    atomicAdd(o + 3, aw);
}

// ---------------------------------------------------------------------------
extern "C" void kernel_launch(void* const* d_in, const int* in_sizes, int n_in,
                              void* d_out, int out_size) {
    const float* dh   = (const float*)d_in[0];   // (32, 1024)
    const float* enc  = (const float*)d_in[1];   // (32, 2048, 1024)
    const int*   mask = (const int*)d_in[2];     // (32, 2048)
    const float* W    = (const float*)d_in[3];   // (2048, 1024)
    const float* ba   = (const float*)d_in[4];   // (1024,)
    const float* vw   = (const float*)d_in[5];   // (1024,)

    float* out  = (float*)d_out;
    float* ctx  = out;                 // (32, 1024)
    float* attw = out + BB * ND;       // (32, 2048)

    cudaFuncSetAttribute(score_gemm, cudaFuncAttributeMaxDynamicSharedMemorySize, GEMM_SMEM);

    convert_kernel<<<8192, 256>>>(enc);
    transpose_kernel<<<dim3(32, 32), dim3(32, 8)>>>(W);
    prep_kernel<<<dim3(32, 4), 256>>>(dh, W, ba, ctx);
    score_gemm<<<dim3(8, 512), 256, GEMM_SMEM>>>(vw);
    softmax_kernel<<<32, 256>>>(mask, attw);
    context_kernel<<<dim3(16, 32), 256>>>(attw, ctx);
}

// round 8
// speedup vs baseline: 1.1118x; 1.0294x over previous
#include <cuda_runtime.h>
#include <cuda_fp16.h>
#include <cstdint>

#define BB   32
#define SS   2048
#define ND   1024

// Scratch (allocation-free rule: __device__ globals)
__device__ float  g_scores[BB * SS];
__device__ float  g_decb[BB * ND];
__device__ __half g_Bth[ND * ND];         // W_enc^T fp16: Bth[n][k] = W[1024+k][n]
__device__ __half g_ench[BB * SS * ND];   // encoder_outputs in fp16

// ---------------------------------------------------------------- helpers
__device__ __forceinline__ float fast_tanh(float x) {
    float y;
    asm("tanh.approx.f32 %0, %1;" : "=f"(y) : "f"(x));
    return y;
}
__device__ __forceinline__ uint32_t smem_u32(const void* p) {
    uint32_t a;
    asm("{ .reg .u64 t; cvta.to.shared.u64 t, %1; cvt.u32.u64 %0, t; }" : "=r"(a) : "l"(p));
    return a;
}

// ---------------------------------------------------------------------------
// Kernel A: convert encoder_outputs fp32 -> fp16 (64M elements)
// ---------------------------------------------------------------------------
__global__ void convert_kernel(const float* __restrict__ enc) {
    const uint32_t t = blockIdx.x * 256 + threadIdx.x;     // 2M threads
    uint2* outp = (uint2*)g_ench;
#pragma unroll
    for (int i = 0; i < 8; i++) {
        const uint32_t idx = t + (uint32_t)i * (8192 * 256);   // float4 index
        const float4 v = *(const float4*)(enc + (size_t)idx * 4);
        __half2 h0 = __floats2half2_rn(v.x, v.y);
        __half2 h1 = __floats2half2_rn(v.z, v.w);
        uint2 o;
        o.x = *(uint32_t*)&h0;
        o.y = *(uint32_t*)&h1;
        outp[idx] = o;
    }
}

// ---------------------------------------------------------------------------
// Kernel 0: transpose W_enc -> g_Bth (fp16)
// ---------------------------------------------------------------------------
__global__ void transpose_kernel(const float* __restrict__ W) {
    __shared__ float t[32][33];
    const int kb = blockIdx.x * 32, nb = blockIdx.y * 32;
    const int tx = threadIdx.x, ty = threadIdx.y;
#pragma unroll
    for (int i = 0; i < 32; i += 8)
        t[ty + i][tx] = W[(size_t)(1024 + kb + ty + i) * 1024 + nb + tx];
    __syncthreads();
#pragma unroll
    for (int i = 0; i < 32; i += 8)
        g_Bth[(size_t)(nb + ty + i) * 1024 + kb + tx] = __float2half_rn(t[tx][ty + i]);
}

// ---------------------------------------------------------------------------
// Kernel 1: dec_base = dh @ W_dec + b_attn; zero score scratch + ctx output
// ---------------------------------------------------------------------------
__global__ void prep_kernel(const float* __restrict__ dh,
                            const float* __restrict__ W,
                            const float* __restrict__ b_attn,
                            float* __restrict__ out_ctx) {
    const int b   = blockIdx.x;
    const int dc  = blockIdx.y;
    const int tid = threadIdx.x;
    const int blk = b * 4 + dc;

    for (int i = blk * 256 + tid; i < BB * SS; i += 128 * 256) g_scores[i] = 0.f;
    for (int i = blk * 256 + tid; i < BB * ND; i += 128 * 256) out_ctx[i] = 0.f;

    __shared__ float sh[ND];
    for (int i = tid; i < ND; i += 256) sh[i] = dh[b * ND + i];
    __syncthreads();

    const int d0 = dc * 256 + tid;
    float a = b_attn[d0];
#pragma unroll 8
    for (int e = 0; e < ND; e++)
        a += sh[e] * W[(size_t)e * ND + d0];
    g_decb[b * ND + d0] = a;
}

// ---------------------------------------------------------------------------
// Kernel 2: enc_proj GEMM, fp16 mma.sync m16n8k16, 128x128 tile, BK=64,
//   3-stage cp.async ring (96KB), ONE sync per BK=64, FULL unroll (16 iters),
//   fused tanh + v-dot.
//   Stage layout = 4 panels of 8KB: Ak0 | Ak1 | Bk0 | Bk1. Each panel has
//   64B rows (32 halfs) -> conflict-free LDS.128 fragment loads (R7 pattern).
//   Ring safety: sync at top of iter kt ensures stage kt-1 (slot (kt+2)%3)
//   reads are done before the loads for stage kt+2 reuse that slot.
//   Uniform commit per iter: at iter kt, commits 0..kt+1 issued; wait_group 1
//   => commit kt (stage kt) complete.
//   K-permutation identical on A and B (exact): thread k-window = (lane&3)*8.
// ---------------------------------------------------------------------------
#define PAN       8192
#define STGB      (4 * PAN)                // 32 KB per stage
#define GEMM_SMEM (3 * STGB)               // 96 KB

__global__ __launch_bounds__(256, 2) void score_gemm(const float* __restrict__ vw) {
    extern __shared__ char smc[];
    const uint32_t sb = smem_u32(smc);
    const int tid  = threadIdx.x;
    const int lane = tid & 31;
    const int warp = tid >> 5;
    const int wm   = warp >> 1;              // 0..3
    const int wn   = warp & 1;               // 0..1
    const int n0   = blockIdx.x * 128;
    const int m0   = blockIdx.y * 128;

    // cp.async mapping: q = tid + i*256 (i=0..3): r = tid>>3 + 32*i, c = tid&7.
    const int rr = tid >> 3, cc = tid & 7;
    const char* pa = (const char*)(g_ench + (size_t)(m0 + rr) * 1024 + cc * 8);
    const char* pb = (const char*)(g_Bth  + (size_t)(n0 + rr) * 1024 + cc * 8);
    const uint32_t dA = sb + (uint32_t)((cc >> 2) * PAN + rr * 64 + (cc & 3) * 16);
    const uint32_t dB = dA + 2 * PAN;
    // per-i increments: src += i*32 rows = i*65536 B ; dst += i*32*64 = i*2048 B

#define LOAD_STAGE(kt, st)                                                      \
    do {                                                                        \
        const uint32_t so = (uint32_t)(st) * STGB;                              \
        const int kb_ = (kt) * 128;  /* BK=64 halfs = 128 B */                  \
        _Pragma("unroll")                                                       \
        for (int i_ = 0; i_ < 4; i_++) {                                        \
            asm volatile("cp.async.cg.shared.global [%0], [%1], 16;"            \
                         :: "r"(dA + so + i_ * 2048), "l"(pa + kb_ + i_ * 65536)); \
            asm volatile("cp.async.cg.shared.global [%0], [%1], 16;"            \
                         :: "r"(dB + so + i_ * 2048), "l"(pb + kb_ + i_ * 65536)); \
        }                                                                       \
    } while (0)

    float acc[2][8][4];
#pragma unroll
    for (int i = 0; i < 2; i++)
#pragma unroll
        for (int j = 0; j < 8; j++)
#pragma unroll
            for (int c = 0; c < 4; c++) acc[i][j][c] = 0.f;

    // preamble: stages 0,1 in flight
    LOAD_STAGE(0, 0);
    asm volatile("cp.async.commit_group;" ::: "memory");
    LOAD_STAGE(1, 1);
    asm volatile("cp.async.commit_group;" ::: "memory");

    const uint32_t koff = (lane & 3) * 16;
    const uint32_t aoff = (uint32_t)(wm * 32 + (lane >> 2)) * 64 + koff;
    const uint32_t boff = (uint32_t)(wn * 64 + (lane >> 2)) * 64 + koff + 2 * PAN;

#pragma unroll
    for (int kt = 0; kt < 16; kt++) {
        const int st = kt % 3;
        asm volatile("cp.async.wait_group 1;" ::: "memory");
        __syncthreads();

        // prefetch stage kt+2 into slot (kt+2)%3 (freed by iter kt-1)
        if (kt < 14) LOAD_STAGE(kt + 2, (kt + 2) % 3);
        asm volatile("cp.async.commit_group;" ::: "memory");

        const uint32_t Astg = sb + (uint32_t)st * STGB;

#pragma unroll
        for (int s = 0; s < 2; s++) {           // two k32 panels
            const uint32_t Asb = Astg + (uint32_t)s * PAN + aoff;
            const uint32_t Bsb = Astg + (uint32_t)s * PAN + boff;

            uint32_t ah[4][4];
#pragma unroll
            for (int rdx = 0; rdx < 4; rdx++)
                asm volatile("ld.shared.v4.u32 {%0,%1,%2,%3}, [%4];"
                             : "=r"(ah[rdx][0]), "=r"(ah[rdx][1]),
                               "=r"(ah[rdx][2]), "=r"(ah[rdx][3])
                             : "r"(Asb + rdx * 512));

#pragma unroll
            for (int jh = 0; jh < 2; jh++) {
                uint32_t bh[4][4];
#pragma unroll
                for (int j = 0; j < 4; j++)
                    asm volatile("ld.shared.v4.u32 {%0,%1,%2,%3}, [%4];"
                                 : "=r"(bh[j][0]), "=r"(bh[j][1]),
                                   "=r"(bh[j][2]), "=r"(bh[j][3])
                                 : "r"(Bsb + (jh * 4 + j) * 512));
#pragma unroll
                for (int i = 0; i < 2; i++)
#pragma unroll
                    for (int j = 0; j < 4; j++)
#pragma unroll
                        for (int u = 0; u < 2; u++) {
                            const int jj = jh * 4 + j;
                            asm volatile(
                                "mma.sync.aligned.m16n8k16.row.col.f32.f16.f16.f32 "
                                "{%0,%1,%2,%3}, {%4,%5,%6,%7}, {%8,%9}, {%0,%1,%2,%3};"
                                : "+f"(acc[i][jj][0]), "+f"(acc[i][jj][1]),
                                  "+f"(acc[i][jj][2]), "+f"(acc[i][jj][3])
                                : "r"(ah[2 * i][2 * u]), "r"(ah[2 * i + 1][2 * u]),
                                  "r"(ah[2 * i][2 * u + 1]), "r"(ah[2 * i + 1][2 * u + 1]),
                                  "r"(bh[j][2 * u]), "r"(bh[j][2 * u + 1]));
                        }
            }
        }
    }
#undef LOAD_STAGE

    // Epilogue: energy = tanh(acc + dec_base[b][col]); score partial = energy . v_w
    const int b = m0 >> 11;
    float eadd[16], vv[16];
#pragma unroll
    for (int j = 0; j < 8; j++)
#pragma unroll
        for (int c = 0; c < 2; c++) {
            const int col = n0 + wn * 64 + j * 8 + (lane & 3) * 2 + c;
            eadd[j * 2 + c] = g_decb[b * ND + col];
            vv[j * 2 + c]   = vw[col];
        }

#pragma unroll
    for (int i = 0; i < 2; i++)
#pragma unroll
        for (int h = 0; h < 2; h++) {
            float p = 0.f;
#pragma unroll
            for (int j = 0; j < 8; j++)
#pragma unroll
                for (int c = 0; c < 2; c++)
                    p += fast_tanh(acc[i][j][h * 2 + c] + eadd[j * 2 + c]) * vv[j * 2 + c];
            p += __shfl_xor_sync(0xffffffffu, p, 1);
            p += __shfl_xor_sync(0xffffffffu, p, 2);
            if ((lane & 3) == 0) {
                const int row = m0 + wm * 32 + i * 16 + h * 8 + (lane >> 2);
                atomicAdd(&g_scores[row], p);
            }
        }
}

// ---------------------------------------------------------------------------
// Kernel 3: masked softmax over S per batch
// ---------------------------------------------------------------------------
__global__ void softmax_kernel(const int* __restrict__ mask,
                               float* __restrict__ out_w) {
    const int b = blockIdx.x;
    const int tid = threadIdx.x;
    __shared__ float red[256];

    float ls[8];
#pragma unroll
    for (int i = 0; i < 8; i++) {
        const int s = tid + i * 256;
        const float sc = g_scores[b * SS + s];
        ls[i] = (mask[b * SS + s] == 0) ? -1e9f : sc;
    }
    float mx = ls[0];
#pragma unroll
    for (int i = 1; i < 8; i++) mx = fmaxf(mx, ls[i]);
    red[tid] = mx;
    __syncthreads();
    for (int off = 128; off > 0; off >>= 1) {
        if (tid < off) red[tid] = fmaxf(red[tid], red[tid + off]);
        __syncthreads();
    }
    mx = red[0];
    __syncthreads();

    float ex[8];
    float sum = 0.f;
#pragma unroll
    for (int i = 0; i < 8; i++) {
        ex[i] = __expf(ls[i] - mx);
        sum += ex[i];
    }
    red[tid] = sum;
    __syncthreads();
    for (int off = 128; off > 0; off >>= 1) {
        if (tid < off) red[tid] += red[tid + off];
        __syncthreads();
    }
    const float inv = 1.f / red[0];
#pragma unroll
    for (int i = 0; i < 8; i++)
        out_w[b * SS + tid + i * 256] = ex[i] * inv;
}

// ---------------------------------------------------------------------------
// Kernel 4: context = attn_weights @ encoder_outputs (fp16 enc, fp32 accum)
// ---------------------------------------------------------------------------
__global__ void context_kernel(const float* __restrict__ w,
                               float* __restrict__ ctx) {
    const int b = blockIdx.y;
    const int ch = blockIdx.x;
    const int tid = threadIdx.x;
    __shared__ float ws[128];
    const int s0 = ch * 128;
    if (tid < 128) ws[tid] = w[b * SS + s0 + tid];
    __syncthreads();

    float ax = 0.f, ay = 0.f, az = 0.f, aw = 0.f;
    const __half* base = g_ench + ((size_t)b * SS + s0) * 1024 + tid * 4;
#pragma unroll 4
    for (int s = 0; s < 128; s++) {
        const uint2 u = *(const uint2*)(base + (size_t)s * 1024);
        const float2 f01 = __half22float2(*(const __half2*)&u.x);
        const float2 f23 = __half22float2(*(const __half2*)&u.y);
        const float wv = ws[s];
        ax += wv * f01.x;
        ay += wv * f01.y;
        az += wv * f23.x;
        aw += wv * f23.y;
    }
    float* o = ctx + b * ND + tid * 4;
    atomicAdd(o + 0, ax);
    atomicAdd(o + 1, ay);
    atomicAdd(o + 2, az);
    atomicAdd(o + 3, aw);
}

// ---------------------------------------------------------------------------
extern "C" void kernel_launch(void* const* d_in, const int* in_sizes, int n_in,
                              void* d_out, int out_size) {
    const float* dh   = (const float*)d_in[0];   // (32, 1024)
    const float* enc  = (const float*)d_in[1];   // (32, 2048, 1024)
    const int*   mask = (const int*)d_in[2];     // (32, 2048)
    const float* W    = (const float*)d_in[3];   // (2048, 1024)
    const float* ba   = (const float*)d_in[4];   // (1024,)
    const float* vw   = (const float*)d_in[5];   // (1024,)

    float* out  = (float*)d_out;
    float* ctx  = out;                 // (32, 1024)
    float* attw = out + BB * ND;       // (32, 2048)

    cudaFuncSetAttribute(score_gemm, cudaFuncAttributeMaxDynamicSharedMemorySize, GEMM_SMEM);

    convert_kernel<<<8192, 256>>>(enc);
    transpose_kernel<<<dim3(32, 32), dim3(32, 8)>>>(W);
    prep_kernel<<<dim3(32, 4), 256>>>(dh, W, ba, ctx);
    score_gemm<<<dim3(8, 512), 256, GEMM_SMEM>>>(vw);
    softmax_kernel<<<32, 256>>>(mask, attw);
    context_kernel<<<dim3(16, 32), 256>>>(attw, ctx);
}